// round 9
// baseline (speedup 1.0000x reference)
#include <cuda_runtime.h>
#include <math.h>

// Problem constants: N=8, S=8192, C=1, K=1024, V=64
#define NS_TOTAL 65536
#define VDIM 64
#define KCW 1024
#define BM 64                  // rows per CTA (grid 1024)
#define BK 256
#define NCHUNK (KCW / BK)      // 4

#define XST 130                // x stride: 2*BM + 2
#define EST 258                // e stride: BK + 2
#define XS_FLOATS (VDIM * XST) // 8320
#define ES_FLOATS (VDIM * EST) // 16512
#define SMEM_BYTES 120000      // padded: forces 1 CTA/SM

typedef unsigned long long ull;

__device__ int g_counts[KCW];   // zero at load; entropy kernel re-zeroes after use

// Packed fp32x2 ops (split to scalar FFMA by ptxas on this target, but IEEE-rn
// per lane either way — keeps the proven bit-exact accumulation order).
__device__ __forceinline__ ull ffma2(ull a, ull b, ull c) {
    ull d;
    asm("fma.rn.f32x2 %0, %1, %2, %3;" : "=l"(d) : "l"(a), "l"(b), "l"(c));
    return d;
}
__device__ __forceinline__ ull fmul2(ull a, ull b) {
    ull d;
    asm("mul.rn.f32x2 %0, %1, %2;" : "=l"(d) : "l"(a), "l"(b));
    return d;
}
__device__ __forceinline__ ull fadd2(ull a, ull b) {
    ull d;
    asm("add.rn.f32x2 %0, %1, %2;" : "=l"(d) : "l"(a), "l"(b));
    return d;
}
__device__ __forceinline__ void unpack2(ull v, float& lo, float& hi) {
    unsigned int l, h;
    asm("mov.b64 {%0, %1}, %2;" : "=r"(l), "=r"(h) : "l"(v));
    lo = __uint_as_float(l);
    hi = __uint_as_float(h);
}
__device__ __forceinline__ ull pack2(float lo, float hi) {
    ull v;
    asm("mov.b64 %0, {%1, %2};" : "=l"(v) : "f"(lo), "f"(hi));
    return v;
}

// e-tile bank swizzle: float-index idx -> idx ^ (4*((v>>2)&7)).
// Touches float-idx bits [2..4] only: keeps ull pair adjacency/alignment and
// commutes with +32*m (bit5+). Turns 4-way STS conflicts into 2-way.
#define ESWZ(v) (4 * (((v) >> 2) & 7))

// ---------------------------------------------------------------------------
// Kernel 1: fused GEMM + per-chunk codeword norms + argmin + histogram + outputs
// grid 1024 (64 samples each), 256 threads, 1 CTA/SM (smem-pinned)
// thread tile: 4 rows x 16 codewords (8 packed pairs)
// ---------------------------------------------------------------------------
__global__ __launch_bounds__(256, 1)
void vq_main_kernel(const float* __restrict__ x, const float* __restrict__ emb,
                    float* __restrict__ out0, float* __restrict__ out1,
                    float* __restrict__ out2) {
    extern __shared__ float sm[];
    float* xs2  = sm;                          // [VDIM][XST] duplicated x pairs
    float* es   = sm + XS_FLOATS;              // [VDIM][EST] e chunk (transposed, swizzled)
    float* en_s = sm + XS_FLOATS + ES_FLOATS;  // [KCW] codeword norms (per-chunk valid)
    float* xn_s = en_s + KCW;                  // [BM] row norms
    // post-loop overlays on es:
    float* red_val = es;                       // [16][66]
    int*   red_idx = (int*)(es + 1056);        // [16][66]
    int*   amin_s  = (int*)(es + 2112);        // [BM]
    float* rowsum  = es + 2176;                // [BM]

    const int tid  = threadIdx.x;
    const int tx   = tid & 15;                 // 16 codeword-pair groups
    const int ty   = tid >> 4;                 // 16 row groups
    const int row0 = blockIdx.x * BM;

    // ---- load x tile (coalesced float4), store duplicated pairs (v-major) ----
    const float4* x4 = reinterpret_cast<const float4*>(x) + (size_t)row0 * (VDIM / 4);
    #pragma unroll
    for (int t = 0; t < 4; t++) {
        int lin4 = tid + t * 256;              // 1024 float4
        int r    = lin4 >> 4;
        int v4   = lin4 & 15;
        float4 val = x4[lin4];
        *reinterpret_cast<float2*>(xs2 + (v4 * 4 + 0) * XST + 2 * r) = make_float2(val.x, val.x);
        *reinterpret_cast<float2*>(xs2 + (v4 * 4 + 1) * XST + 2 * r) = make_float2(val.y, val.y);
        *reinterpret_cast<float2*>(xs2 + (v4 * 4 + 2) * XST + 2 * r) = make_float2(val.z, val.z);
        *reinterpret_cast<float2*>(xs2 + (v4 * 4 + 3) * XST + 2 * r) = make_float2(val.w, val.w);
    }
    __syncthreads();

    // ---- row norms ||x_r||^2 (sequential mul+add, v ascending) ----
    if (tid < BM) {
        float acc = 0.0f;
        const float* xr = xs2 + 2 * tid;
        #pragma unroll 8
        for (int v = 0; v < VDIM; v++) {
            float xv = xr[v * XST];
            acc = __fadd_rn(acc, __fmul_rn(xv, xv));
        }
        xn_s[tid] = acc;
    }

    float minv[4];
    int   mini[4];
    #pragma unroll
    for (int i = 0; i < 4; i++) { minv[i] = 3.402823466e38f; mini[i] = 0; }

    const ull NEG2 = 0xC0000000C0000000ULL;    // {-2.0f, -2.0f}

    // thread covers rows r_i = ty + 16*i (i<4), codewords k = c*256 + 32*m + 2*tx + {0,1} (m<8)
    for (int c = 0; c < NCHUNK; c++) {
        if (c > 0) __syncthreads();            // compute done before overwriting es
        const float4* e4 = reinterpret_cast<const float4*>(emb) + (size_t)c * (BK * VDIM / 4);
        #pragma unroll
        for (int t = 0; t < 16; t++) {
            int lin4 = tid + t * 256;          // 4096 float4
            int k    = lin4 >> 4;
            int v4   = lin4 & 15;
            float4 val = e4[lin4];
            int swz = 4 * (v4 & 7);            // ESWZ(4*v4+j) == ESWZ(4*v4)
            es[(((v4 * 4 + 0) * EST + k)) ^ swz] = val.x;
            es[(((v4 * 4 + 1) * EST + k)) ^ swz] = val.y;
            es[(((v4 * 4 + 2) * EST + k)) ^ swz] = val.z;
            es[(((v4 * 4 + 3) * EST + k)) ^ swz] = val.w;
        }
        __syncthreads();

        // ---- per-chunk codeword norms from smem (thread-per-codeword,
        //      sequential mul+add, v ascending — bit-identical to reference) ----
        {
            float acc = 0.0f;
            #pragma unroll 8
            for (int v = 0; v < VDIM; v++) {
                float ev = es[(v * EST + tid) ^ ESWZ(v)];
                acc = __fadd_rn(acc, __fmul_rn(ev, ev));
            }
            en_s[c * BK + tid] = acc;
        }
        __syncthreads();                       // en_s visible before epilogue reads

        ull acc[4][8];
        #pragma unroll
        for (int i = 0; i < 4; i++)
            #pragma unroll
            for (int m = 0; m < 8; m++) acc[i][m] = 0ULL;

        const int txk = 2 * tx;
        const int tyk = 2 * ty;
        // sequential FMA over v=0..63, single accumulator per (row, codeword)
        #pragma unroll 8
        for (int v = 0; v < VDIM; v++) {
            int ei = (v * EST + txk) ^ ESWZ(v);
            ull ep[8];
            #pragma unroll
            for (int m = 0; m < 8; m++)
                ep[m] = *reinterpret_cast<const ull*>(es + ei + 32 * m);
            ull xp[4];
            #pragma unroll
            for (int i = 0; i < 4; i++)
                xp[i] = *reinterpret_cast<const ull*>(xs2 + v * XST + tyk + 32 * i);
            #pragma unroll
            for (int i = 0; i < 4; i++)
                #pragma unroll
                for (int m = 0; m < 8; m++)
                    acc[i][m] = ffma2(xp[i], ep[m], acc[i][m]);
        }

        // score = fl( fl( xn - fl(2*dot) ) + en ) via packed ops (exact per lane)
        ull xn2[4];
        #pragma unroll
        for (int i = 0; i < 4; i++) {
            float xnv = xn_s[ty + 16 * i];
            xn2[i] = pack2(xnv, xnv);
        }
        #pragma unroll
        for (int m = 0; m < 8; m++) {
            int kk = 32 * m + txk;             // local codeword pair base
            int k0 = c * BK + kk;              // global
            ull en2 = *reinterpret_cast<const ull*>(en_s + k0);
            #pragma unroll
            for (int i = 0; i < 4; i++) {
                ull s2 = fadd2(fadd2(xn2[i], fmul2(acc[i][m], NEG2)), en2);
                float s0, s1;
                unpack2(s2, s0, s1);
                if (s0 < minv[i]) { minv[i] = s0; mini[i] = k0; }
                if (s1 < minv[i]) { minv[i] = s1; mini[i] = k0 + 1; }
            }
        }
    }

    // ---- cross-thread argmin reduction (16 candidates per row) ----
    __syncthreads();
    #pragma unroll
    for (int i = 0; i < 4; i++) {
        int r = ty + 16 * i;
        red_val[tx * 66 + r] = minv[i];
        red_idx[tx * 66 + r] = mini[i];
    }
    __syncthreads();
    if (tid < BM) {
        int r = tid;
        float bv = red_val[r];
        int   bi = red_idx[r];
        #pragma unroll
        for (int j = 1; j < 16; j++) {
            float v  = red_val[j * 66 + r];
            int   id = red_idx[j * 66 + r];
            if (v < bv || (v == bv && id < bi)) { bv = v; bi = id; }
        }
        amin_s[r] = bi;
        rowsum[r] = 0.0f;
        atomicAdd(&g_counts[bi], 1);
    }
    __syncthreads();

    // ---- outputs: out0 = fl(fl(o - x) + x), out1 = out2 = sum_v (x-o)^2 ----
    #pragma unroll 4
    for (int t = 0; t < 16; t++) {
        int i = t * 256 + tid;                 // 4096 elements
        int r = i >> 6;
        int v = i & 63;
        float o  = emb[amin_s[r] * VDIM + v];
        float xv = xs2[v * XST + 2 * r];
        float d  = __fsub_rn(xv, o);
        float sq = __fmul_rn(d, d);
        #pragma unroll
        for (int off = 16; off > 0; off >>= 1)
            sq += __shfl_down_sync(0xffffffffu, sq, off);
        if ((tid & 31) == 0) atomicAdd(&rowsum[r], sq);   // 2 adds/row: order-invariant
        out0[(size_t)(row0 + r) * VDIM + v] = __fadd_rn(__fsub_rn(o, xv), xv);
    }
    __syncthreads();
    if (tid < BM) {
        float s = rowsum[tid];
        out1[row0 + tid] = s;
        out2[row0 + tid] = s;
    }
}

// ---------------------------------------------------------------------------
// Kernel 2: entropy of the histogram; re-zeroes counts for the next replay
// (device globals start zeroed at module load, so every execution sees a
//  clean histogram — deterministic under graph replay)
// ---------------------------------------------------------------------------
__global__ void vq_entropy_kernel(float* __restrict__ ent) {
    __shared__ float warpsum[32];
    int k = threadIdx.x;                   // 1024 threads
    int c = g_counts[k];
    g_counts[k] = 0;
    float term = 0.0f;
    if (c > 0) {
        float p = (float)c * (1.0f / 65536.0f);
        term = -p * logf(p);
    }
    #pragma unroll
    for (int off = 16; off > 0; off >>= 1)
        term += __shfl_down_sync(0xffffffffu, term, off);
    int lane = k & 31, wid = k >> 5;
    if (lane == 0) warpsum[wid] = term;
    __syncthreads();
    if (wid == 0) {
        float s = warpsum[lane];
        #pragma unroll
        for (int off = 16; off > 0; off >>= 1)
            s += __shfl_down_sync(0xffffffffu, s, off);
        if (lane == 0) *ent = s;
    }
}

// ---------------------------------------------------------------------------
extern "C" void kernel_launch(void* const* d_in, const int* in_sizes, int n_in,
                              void* d_out, int out_size) {
    const float* x;
    const float* emb;
    if (in_sizes[0] == NS_TOTAL * VDIM) {
        x   = (const float*)d_in[0];
        emb = (const float*)d_in[1];
    } else {
        x   = (const float*)d_in[1];
        emb = (const float*)d_in[0];
    }

    float* out0 = (float*)d_out;                        // 65536*64
    float* out1 = out0 + (size_t)NS_TOTAL * VDIM;       // 65536
    float* out2 = out1 + NS_TOTAL;                      // 65536
    float* ent  = out2 + NS_TOTAL;                      // 1

    cudaFuncSetAttribute(vq_main_kernel,
                         cudaFuncAttributeMaxDynamicSharedMemorySize, SMEM_BYTES);

    vq_main_kernel<<<1024, 256, SMEM_BYTES>>>(x, emb, out0, out1, out2);
    vq_entropy_kernel<<<1, 1024>>>(ent);
}

// round 10
// speedup vs baseline: 1.0430x; 1.0430x over previous
#include <cuda_runtime.h>
#include <math.h>

// Problem constants: N=8, S=8192, C=1, K=1024, V=64
#define NS_TOTAL 65536
#define VDIM 64
#define KCW 1024
#define BM 64                  // rows per CTA (grid 1024)
#define BK 256
#define NCHUNK (KCW / BK)      // 4
#define GRID 1024

#define XST 130                // x stride: 2*BM + 2
#define EST 258                // e stride: BK + 2
#define XS_FLOATS (VDIM * XST) // 8320
#define ES_FLOATS (VDIM * EST) // 16512
#define SMEM_BYTES 120000      // padded: forces 1 CTA/SM

typedef unsigned long long ull;

__device__ float g_en[KCW];
__device__ int   g_counts[KCW];   // zero at load; last CTA re-zeroes each run
__device__ int   g_done;          // zero at load; last CTA resets each run

// Packed fp32x2 ops (split to scalar FFMA by ptxas on this target, but IEEE-rn
// per lane either way — keeps the proven bit-exact accumulation order).
__device__ __forceinline__ ull ffma2(ull a, ull b, ull c) {
    ull d;
    asm("fma.rn.f32x2 %0, %1, %2, %3;" : "=l"(d) : "l"(a), "l"(b), "l"(c));
    return d;
}
__device__ __forceinline__ ull fmul2(ull a, ull b) {
    ull d;
    asm("mul.rn.f32x2 %0, %1, %2;" : "=l"(d) : "l"(a), "l"(b));
    return d;
}
__device__ __forceinline__ ull fadd2(ull a, ull b) {
    ull d;
    asm("add.rn.f32x2 %0, %1, %2;" : "=l"(d) : "l"(a), "l"(b));
    return d;
}
__device__ __forceinline__ void unpack2(ull v, float& lo, float& hi) {
    unsigned int l, h;
    asm("mov.b64 {%0, %1}, %2;" : "=r"(l), "=r"(h) : "l"(v));
    lo = __uint_as_float(l);
    hi = __uint_as_float(h);
}
__device__ __forceinline__ ull pack2(float lo, float hi) {
    ull v;
    asm("mov.b64 %0, {%1, %2};" : "=l"(v) : "f"(lo), "f"(hi));
    return v;
}

// e-tile bank swizzle: float-index idx -> idx ^ (4*((v>>2)&7)).
#define ESWZ(v) (4 * (((v) >> 2) & 7))

// ---------------------------------------------------------------------------
// Kernel 1: codeword norms via coalesced smem staging.
// 16 blocks x 256 threads; each block stages 64 codewords then 64 threads
// compute the bit-exact sequential (mul+add, v ascending) norm from smem.
// ---------------------------------------------------------------------------
__global__ void vq_prep_kernel(const float* __restrict__ emb) {
    __shared__ float se[64 * 65];
    const int tid = threadIdx.x;
    const int kb  = blockIdx.x * 64;
    const float4* e4 = reinterpret_cast<const float4*>(emb) + (size_t)kb * (VDIM / 4);
    #pragma unroll
    for (int t = 0; t < 4; t++) {
        int idx = tid + t * 256;           // 1024 float4
        int r   = idx >> 4;
        int v4  = idx & 15;
        float4 f = e4[idx];
        float* d = se + r * 65 + v4 * 4;
        d[0] = f.x; d[1] = f.y; d[2] = f.z; d[3] = f.w;
    }
    __syncthreads();
    if (tid < 64) {
        const float* er = se + tid * 65;
        float acc = 0.0f;
        #pragma unroll 8
        for (int v = 0; v < VDIM; v++)
            acc = __fadd_rn(acc, __fmul_rn(er[v], er[v]));
        g_en[kb + tid] = acc;
    }
}

// ---------------------------------------------------------------------------
// Kernel 2: fused GEMM + argmin + histogram + outputs + (last CTA) entropy
// grid 1024 (64 samples each), 256 threads, 1 CTA/SM (smem-pinned)
// thread tile: 4 rows x 16 codewords (8 packed pairs)
// ---------------------------------------------------------------------------
__global__ __launch_bounds__(256, 1)
void vq_main_kernel(const float* __restrict__ x, const float* __restrict__ emb,
                    float* __restrict__ out0, float* __restrict__ out1,
                    float* __restrict__ out2, float* __restrict__ ent) {
    extern __shared__ float sm[];
    float* xs2  = sm;                          // [VDIM][XST] duplicated x pairs
    float* es   = sm + XS_FLOATS;              // [VDIM][EST] e chunk (transposed, swizzled)
    float* en_s = sm + XS_FLOATS + ES_FLOATS;  // [KCW] codeword norms
    float* xn_s = en_s + KCW;                  // [BM] row norms
    // post-loop overlays on es:
    float* red_val = es;                       // [16][66]
    int*   red_idx = (int*)(es + 1056);        // [16][66]
    int*   amin_s  = (int*)(es + 2112);        // [BM]
    float* rowsum  = es + 2176;                // [BM]

    const int tid  = threadIdx.x;
    const int tx   = tid & 15;                 // 16 codeword-pair groups
    const int ty   = tid >> 4;                 // 16 row groups
    const int row0 = blockIdx.x * BM;

    // ---- load x tile (coalesced float4), store duplicated pairs (v-major) ----
    const float4* x4 = reinterpret_cast<const float4*>(x) + (size_t)row0 * (VDIM / 4);
    #pragma unroll
    for (int t = 0; t < 4; t++) {
        int lin4 = tid + t * 256;              // 1024 float4
        int r    = lin4 >> 4;
        int v4   = lin4 & 15;
        float4 val = x4[lin4];
        *reinterpret_cast<float2*>(xs2 + (v4 * 4 + 0) * XST + 2 * r) = make_float2(val.x, val.x);
        *reinterpret_cast<float2*>(xs2 + (v4 * 4 + 1) * XST + 2 * r) = make_float2(val.y, val.y);
        *reinterpret_cast<float2*>(xs2 + (v4 * 4 + 2) * XST + 2 * r) = make_float2(val.z, val.z);
        *reinterpret_cast<float2*>(xs2 + (v4 * 4 + 3) * XST + 2 * r) = make_float2(val.w, val.w);
    }
    // ---- copy codeword norms into smem (4 per thread) ----
    #pragma unroll
    for (int t = 0; t < 4; t++) en_s[tid + t * 256] = g_en[tid + t * 256];
    __syncthreads();

    // ---- row norms ||x_r||^2 (sequential mul+add, v ascending) ----
    if (tid < BM) {
        float acc = 0.0f;
        const float* xr = xs2 + 2 * tid;
        #pragma unroll 8
        for (int v = 0; v < VDIM; v++) {
            float xv = xr[v * XST];
            acc = __fadd_rn(acc, __fmul_rn(xv, xv));
        }
        xn_s[tid] = acc;
    }

    float minv[4];
    int   mini[4];
    #pragma unroll
    for (int i = 0; i < 4; i++) { minv[i] = 3.402823466e38f; mini[i] = 0; }

    const ull NEG2 = 0xC0000000C0000000ULL;    // {-2.0f, -2.0f}

    // thread covers rows r_i = ty + 16*i (i<4), codewords k = c*256 + 32*m + 2*tx + {0,1} (m<8)
    for (int c = 0; c < NCHUNK; c++) {
        if (c > 0) __syncthreads();            // compute done before overwriting es
        const float4* e4 = reinterpret_cast<const float4*>(emb) + (size_t)c * (BK * VDIM / 4);
        #pragma unroll
        for (int t = 0; t < 16; t++) {
            int lin4 = tid + t * 256;          // 4096 float4
            int k    = lin4 >> 4;
            int v4   = lin4 & 15;
            float4 val = e4[lin4];
            int swz = 4 * (v4 & 7);            // ESWZ(4*v4+j) == ESWZ(4*v4)
            es[(((v4 * 4 + 0) * EST + k)) ^ swz] = val.x;
            es[(((v4 * 4 + 1) * EST + k)) ^ swz] = val.y;
            es[(((v4 * 4 + 2) * EST + k)) ^ swz] = val.z;
            es[(((v4 * 4 + 3) * EST + k)) ^ swz] = val.w;
        }
        __syncthreads();

        ull acc[4][8];
        #pragma unroll
        for (int i = 0; i < 4; i++)
            #pragma unroll
            for (int m = 0; m < 8; m++) acc[i][m] = 0ULL;

        const int txk = 2 * tx;
        const int tyk = 2 * ty;
        // sequential FMA over v=0..63, single accumulator per (row, codeword)
        #pragma unroll 8
        for (int v = 0; v < VDIM; v++) {
            int ei = (v * EST + txk) ^ ESWZ(v);
            ull ep[8];
            #pragma unroll
            for (int m = 0; m < 8; m++)
                ep[m] = *reinterpret_cast<const ull*>(es + ei + 32 * m);
            ull xp[4];
            #pragma unroll
            for (int i = 0; i < 4; i++)
                xp[i] = *reinterpret_cast<const ull*>(xs2 + v * XST + tyk + 32 * i);
            #pragma unroll
            for (int i = 0; i < 4; i++)
                #pragma unroll
                for (int m = 0; m < 8; m++)
                    acc[i][m] = ffma2(xp[i], ep[m], acc[i][m]);
        }

        // score = fl( fl( xn - fl(2*dot) ) + en ) via packed ops (exact per lane)
        ull xn2[4];
        #pragma unroll
        for (int i = 0; i < 4; i++) {
            float xnv = xn_s[ty + 16 * i];
            xn2[i] = pack2(xnv, xnv);
        }
        #pragma unroll
        for (int m = 0; m < 8; m++) {
            int kk = 32 * m + txk;             // local codeword pair base
            int k0 = c * BK + kk;              // global
            ull en2 = *reinterpret_cast<const ull*>(en_s + k0);
            #pragma unroll
            for (int i = 0; i < 4; i++) {
                ull s2 = fadd2(fadd2(xn2[i], fmul2(acc[i][m], NEG2)), en2);
                float s0, s1;
                unpack2(s2, s0, s1);
                if (s0 < minv[i]) { minv[i] = s0; mini[i] = k0; }
                if (s1 < minv[i]) { minv[i] = s1; mini[i] = k0 + 1; }
            }
        }
    }

    // ---- cross-thread argmin reduction (16 candidates per row) ----
    __syncthreads();
    #pragma unroll
    for (int i = 0; i < 4; i++) {
        int r = ty + 16 * i;
        red_val[tx * 66 + r] = minv[i];
        red_idx[tx * 66 + r] = mini[i];
    }
    __syncthreads();
    if (tid < BM) {
        int r = tid;
        float bv = red_val[r];
        int   bi = red_idx[r];
        #pragma unroll
        for (int j = 1; j < 16; j++) {
            float v  = red_val[j * 66 + r];
            int   id = red_idx[j * 66 + r];
            if (v < bv || (v == bv && id < bi)) { bv = v; bi = id; }
        }
        amin_s[r] = bi;
        rowsum[r] = 0.0f;
        atomicAdd(&g_counts[bi], 1);
    }
    __syncthreads();

    // ---- outputs: out0 = fl(fl(o - x) + x), out1 = out2 = sum_v (x-o)^2 ----
    #pragma unroll 4
    for (int t = 0; t < 16; t++) {
        int i = t * 256 + tid;                 // 4096 elements
        int r = i >> 6;
        int v = i & 63;
        float o  = emb[amin_s[r] * VDIM + v];
        float xv = xs2[v * XST + 2 * r];
        float d  = __fsub_rn(xv, o);
        float sq = __fmul_rn(d, d);
        #pragma unroll
        for (int off = 16; off > 0; off >>= 1)
            sq += __shfl_down_sync(0xffffffffu, sq, off);
        if ((tid & 31) == 0) atomicAdd(&rowsum[r], sq);   // 2 adds/row: order-invariant
        out0[(size_t)(row0 + r) * VDIM + v] = __fadd_rn(__fsub_rn(o, xv), xv);
    }
    __syncthreads();
    if (tid < BM) {
        float s = rowsum[tid];
        out1[row0 + tid] = s;
        out2[row0 + tid] = s;
    }

    // ---- last CTA computes entropy and resets state for the next replay ----
    __threadfence();                           // order this CTA's atomics/stores
    __shared__ int is_last;
    __syncthreads();
    if (tid == 0) {
        int d = atomicAdd(&g_done, 1);
        is_last = (d == GRID - 1);
    }
    __syncthreads();
    if (is_last) {
        // 256 threads x 4 bins each
        float term = 0.0f;
        #pragma unroll
        for (int t = 0; t < 4; t++) {
            int k = tid + t * 256;
            int c = g_counts[k];
            g_counts[k] = 0;
            if (c > 0) {
                float p = (float)c * (1.0f / 65536.0f);
                term -= p * logf(p);
            }
        }
        #pragma unroll
        for (int off = 16; off > 0; off >>= 1)
            term += __shfl_down_sync(0xffffffffu, term, off);
        float* wsum = rowsum;                  // reuse smem
        if ((tid & 31) == 0) wsum[tid >> 5] = term;
        __syncthreads();
        if (tid == 0) {
            float s = 0.0f;
            #pragma unroll
            for (int wI = 0; wI < 8; wI++) s += wsum[wI];
            *ent = s;
            g_done = 0;
        }
    }
}

// ---------------------------------------------------------------------------
extern "C" void kernel_launch(void* const* d_in, const int* in_sizes, int n_in,
                              void* d_out, int out_size) {
    const float* x;
    const float* emb;
    if (in_sizes[0] == NS_TOTAL * VDIM) {
        x   = (const float*)d_in[0];
        emb = (const float*)d_in[1];
    } else {
        x   = (const float*)d_in[1];
        emb = (const float*)d_in[0];
    }

    float* out0 = (float*)d_out;                        // 65536*64
    float* out1 = out0 + (size_t)NS_TOTAL * VDIM;       // 65536
    float* out2 = out1 + NS_TOTAL;                      // 65536
    float* ent  = out2 + NS_TOTAL;                      // 1

    cudaFuncSetAttribute(vq_main_kernel,
                         cudaFuncAttributeMaxDynamicSharedMemorySize, SMEM_BYTES);

    vq_prep_kernel<<<16, 256>>>(emb);
    vq_main_kernel<<<GRID, 256, SMEM_BYTES>>>(x, emb, out0, out1, out2, ent);
}

// round 11
// speedup vs baseline: 1.1271x; 1.0806x over previous
#include <cuda_runtime.h>
#include <math.h>

// Problem constants: N=8, S=8192, C=1, K=1024, V=64
#define NS_TOTAL 65536
#define VDIM 64
#define KCW 1024
#define BM 64                  // rows per CTA
#define BK 256
#define NCHUNK (KCW / BK)      // 4
#define GRID 1024
#define THREADS 128

#define XST 132                // x stride: 2*BM + 4 (16B-aligned rows for LDS.128)
#define EST 258                // e stride: BK + 2
#define XS_FLOATS (VDIM * XST) // 8448
#define ES_FLOATS (VDIM * EST) // 16512
#define SMEM_BYTES ((XS_FLOATS + ES_FLOATS + KCW + BM) * 4)   // 104192 -> 2 CTAs/SM

typedef unsigned long long ull;

__device__ float g_en[KCW];
__device__ int   g_counts[KCW];   // zero at load; last CTA re-zeroes each run
__device__ int   g_done;          // zero at load; last CTA resets each run

// Packed fp32x2 ops — IEEE rn per 32-bit lane (native FFMA2 on this part).
__device__ __forceinline__ ull ffma2(ull a, ull b, ull c) {
    ull d;
    asm("fma.rn.f32x2 %0, %1, %2, %3;" : "=l"(d) : "l"(a), "l"(b), "l"(c));
    return d;
}
__device__ __forceinline__ ull fmul2(ull a, ull b) {
    ull d;
    asm("mul.rn.f32x2 %0, %1, %2;" : "=l"(d) : "l"(a), "l"(b));
    return d;
}
__device__ __forceinline__ ull fadd2(ull a, ull b) {
    ull d;
    asm("add.rn.f32x2 %0, %1, %2;" : "=l"(d) : "l"(a), "l"(b));
    return d;
}
__device__ __forceinline__ void unpack2(ull v, float& lo, float& hi) {
    unsigned int l, h;
    asm("mov.b64 {%0, %1}, %2;" : "=r"(l), "=r"(h) : "l"(v));
    lo = __uint_as_float(l);
    hi = __uint_as_float(h);
}
__device__ __forceinline__ ull pack2(float lo, float hi) {
    ull v;
    asm("mov.b64 %0, {%1, %2};" : "=l"(v) : "f"(lo), "f"(hi));
    return v;
}

// e-tile bank swizzle: float-index idx -> idx ^ (4*((v>>2)&7)).
#define ESWZ(v) (4 * (((v) >> 2) & 7))

// ---------------------------------------------------------------------------
// Kernel 1: codeword norms via coalesced smem staging (bit-exact sequential).
// ---------------------------------------------------------------------------
__global__ void vq_prep_kernel(const float* __restrict__ emb) {
    __shared__ float se[64 * 65];
    const int tid = threadIdx.x;
    const int kb  = blockIdx.x * 64;
    const float4* e4 = reinterpret_cast<const float4*>(emb) + (size_t)kb * (VDIM / 4);
    #pragma unroll
    for (int t = 0; t < 4; t++) {
        int idx = tid + t * 256;           // 1024 float4
        int r   = idx >> 4;
        int v4  = idx & 15;
        float4 f = e4[idx];
        float* d = se + r * 65 + v4 * 4;
        d[0] = f.x; d[1] = f.y; d[2] = f.z; d[3] = f.w;
    }
    __syncthreads();
    if (tid < 64) {
        const float* er = se + tid * 65;
        float acc = 0.0f;
        #pragma unroll 8
        for (int v = 0; v < VDIM; v++)
            acc = __fadd_rn(acc, __fmul_rn(er[v], er[v]));
        g_en[kb + tid] = acc;
    }
}

// ---------------------------------------------------------------------------
// Kernel 2: fused GEMM + argmin + histogram + outputs + (last CTA) entropy
// grid 1024 (64 samples each), 128 threads, 2 CTAs/SM (regs+smem sized)
// thread tile: 8 contiguous rows x 16 codewords (8 packed pairs)
// ---------------------------------------------------------------------------
__global__ __launch_bounds__(THREADS, 2)
void vq_main_kernel(const float* __restrict__ x, const float* __restrict__ emb,
                    float* __restrict__ out0, float* __restrict__ out1,
                    float* __restrict__ out2, float* __restrict__ ent) {
    extern __shared__ float sm[];
    float* xs2  = sm;                          // [VDIM][XST] duplicated x pairs
    float* es   = sm + XS_FLOATS;              // [VDIM][EST] e chunk (transposed, swizzled)
    float* en_s = sm + XS_FLOATS + ES_FLOATS;  // [KCW] codeword norms
    float* xn_s = en_s + KCW;                  // [BM] row norms
    // post-loop overlays on es:
    float* red_val = es;                       // [16][66]
    int*   red_idx = (int*)(es + 1056);        // [16][66]
    int*   amin_s  = (int*)(es + 2112);        // [BM]
    float* rowsum  = es + 2176;                // [BM]

    const int tid  = threadIdx.x;
    const int tx   = tid & 15;                 // 16 codeword-pair groups
    const int ty   = tid >> 4;                 // 8 row groups (8 contiguous rows each)
    const int row0 = blockIdx.x * BM;

    // ---- load x tile (coalesced float4), store duplicated pairs (v-major) ----
    const float4* x4 = reinterpret_cast<const float4*>(x) + (size_t)row0 * (VDIM / 4);
    #pragma unroll
    for (int t = 0; t < 8; t++) {
        int lin4 = tid + t * THREADS;          // 1024 float4
        int r    = lin4 >> 4;
        int v4   = lin4 & 15;
        float4 val = x4[lin4];
        *reinterpret_cast<float2*>(xs2 + (v4 * 4 + 0) * XST + 2 * r) = make_float2(val.x, val.x);
        *reinterpret_cast<float2*>(xs2 + (v4 * 4 + 1) * XST + 2 * r) = make_float2(val.y, val.y);
        *reinterpret_cast<float2*>(xs2 + (v4 * 4 + 2) * XST + 2 * r) = make_float2(val.z, val.z);
        *reinterpret_cast<float2*>(xs2 + (v4 * 4 + 3) * XST + 2 * r) = make_float2(val.w, val.w);
    }
    // ---- copy codeword norms into smem (8 per thread) ----
    #pragma unroll
    for (int t = 0; t < 8; t++) en_s[tid + t * THREADS] = g_en[tid + t * THREADS];
    __syncthreads();

    // ---- row norms ||x_r||^2 (sequential mul+add, v ascending) ----
    if (tid < BM) {
        float acc = 0.0f;
        const float* xr = xs2 + 2 * tid;
        #pragma unroll 8
        for (int v = 0; v < VDIM; v++) {
            float xv = xr[v * XST];
            acc = __fadd_rn(acc, __fmul_rn(xv, xv));
        }
        xn_s[tid] = acc;
    }

    float minv[8];
    int   mini[8];
    #pragma unroll
    for (int i = 0; i < 8; i++) { minv[i] = 3.402823466e38f; mini[i] = 0; }

    const ull NEG2 = 0xC0000000C0000000ULL;    // {-2.0f, -2.0f}

    // thread covers rows r_i = 8*ty + i (i<8), codewords k = c*256 + 32*m + 2*tx + {0,1} (m<8)
    for (int c = 0; c < NCHUNK; c++) {
        if (c > 0) __syncthreads();            // compute done before overwriting es
        const float4* e4 = reinterpret_cast<const float4*>(emb) + (size_t)c * (BK * VDIM / 4);
        #pragma unroll
        for (int t = 0; t < 32; t++) {
            int lin4 = tid + t * THREADS;      // 4096 float4
            int k    = lin4 >> 4;
            int v4   = lin4 & 15;
            float4 val = e4[lin4];
            int swz = 4 * (v4 & 7);            // ESWZ(4*v4+j) == ESWZ(4*v4)
            es[(((v4 * 4 + 0) * EST + k)) ^ swz] = val.x;
            es[(((v4 * 4 + 1) * EST + k)) ^ swz] = val.y;
            es[(((v4 * 4 + 2) * EST + k)) ^ swz] = val.z;
            es[(((v4 * 4 + 3) * EST + k)) ^ swz] = val.w;
        }
        __syncthreads();

        ull acc[8][8];
        #pragma unroll
        for (int i = 0; i < 8; i++)
            #pragma unroll
            for (int m = 0; m < 8; m++) acc[i][m] = 0ULL;

        const int txk = 2 * tx;
        // sequential FMA over v=0..63, single accumulator per (row, codeword)
        #pragma unroll 8
        for (int v = 0; v < VDIM; v++) {
            int ei = (v * EST + txk) ^ ESWZ(v);
            ull ep[8];
            #pragma unroll
            for (int m = 0; m < 8; m++)
                ep[m] = *reinterpret_cast<const ull*>(es + ei + 32 * m);
            // x: 8 contiguous duplicated pairs -> 4 x LDS.128
            ull xp[8];
            const ulonglong2* xvp =
                reinterpret_cast<const ulonglong2*>(xs2 + v * XST + ty * 16);
            #pragma unroll
            for (int j = 0; j < 4; j++) {
                ulonglong2 q = xvp[j];
                xp[2 * j]     = q.x;
                xp[2 * j + 1] = q.y;
            }
            #pragma unroll
            for (int i = 0; i < 8; i++)
                #pragma unroll
                for (int m = 0; m < 8; m++)
                    acc[i][m] = ffma2(xp[i], ep[m], acc[i][m]);
        }

        // score = fl( fl( xn - fl(2*dot) ) + en ) via packed ops (exact per lane)
        ull xn2[8];
        #pragma unroll
        for (int i = 0; i < 8; i++) {
            float xnv = xn_s[8 * ty + i];
            xn2[i] = pack2(xnv, xnv);
        }
        #pragma unroll
        for (int m = 0; m < 8; m++) {
            int k0 = c * BK + 32 * m + txk;    // global codeword pair base
            ull en2 = *reinterpret_cast<const ull*>(en_s + k0);
            #pragma unroll
            for (int i = 0; i < 8; i++) {
                ull s2 = fadd2(fadd2(xn2[i], fmul2(acc[i][m], NEG2)), en2);
                float s0, s1;
                unpack2(s2, s0, s1);
                if (s0 < minv[i]) { minv[i] = s0; mini[i] = k0; }
                if (s1 < minv[i]) { minv[i] = s1; mini[i] = k0 + 1; }
            }
        }
    }

    // ---- cross-thread argmin reduction (16 candidates per row) ----
    __syncthreads();
    #pragma unroll
    for (int i = 0; i < 8; i++) {
        int r = 8 * ty + i;
        red_val[tx * 66 + r] = minv[i];
        red_idx[tx * 66 + r] = mini[i];
    }
    __syncthreads();
    if (tid < BM) {
        int r = tid;
        float bv = red_val[r];
        int   bi = red_idx[r];
        #pragma unroll
        for (int j = 1; j < 16; j++) {
            float v  = red_val[j * 66 + r];
            int   id = red_idx[j * 66 + r];
            if (v < bv || (v == bv && id < bi)) { bv = v; bi = id; }
        }
        amin_s[r] = bi;
        rowsum[r] = 0.0f;
        atomicAdd(&g_counts[bi], 1);
    }
    __syncthreads();

    // ---- outputs: out0 = fl(fl(o - x) + x), out1 = out2 = sum_v (x-o)^2 ----
    #pragma unroll 4
    for (int t = 0; t < 32; t++) {
        int i = t * THREADS + tid;             // 4096 elements; warp = half a row
        int r = i >> 6;
        int v = i & 63;
        float o  = emb[amin_s[r] * VDIM + v];
        float xv = xs2[v * XST + 2 * r];
        float d  = __fsub_rn(xv, o);
        float sq = __fmul_rn(d, d);
        #pragma unroll
        for (int off = 16; off > 0; off >>= 1)
            sq += __shfl_down_sync(0xffffffffu, sq, off);
        if ((tid & 31) == 0) atomicAdd(&rowsum[r], sq);   // 2 adds/row: order-invariant
        out0[(size_t)(row0 + r) * VDIM + v] = __fadd_rn(__fsub_rn(o, xv), xv);
    }
    __syncthreads();
    if (tid < BM) {
        float s = rowsum[tid];
        out1[row0 + tid] = s;
        out2[row0 + tid] = s;
    }

    // ---- last CTA computes entropy and resets state for the next replay ----
    __threadfence();                           // order this CTA's atomics/stores
    __shared__ int is_last;
    __syncthreads();
    if (tid == 0) {
        int d = atomicAdd(&g_done, 1);
        is_last = (d == GRID - 1);
    }
    __syncthreads();
    if (is_last) {
        // 128 threads x 8 bins each
        float term = 0.0f;
        #pragma unroll
        for (int t = 0; t < 8; t++) {
            int k = tid + t * THREADS;
            int c = g_counts[k];
            g_counts[k] = 0;
            if (c > 0) {
                float p = (float)c * (1.0f / 65536.0f);
                term -= p * logf(p);
            }
        }
        #pragma unroll
        for (int off = 16; off > 0; off >>= 1)
            term += __shfl_down_sync(0xffffffffu, term, off);
        float* wsum = rowsum;                  // reuse smem
        if ((tid & 31) == 0) wsum[tid >> 5] = term;
        __syncthreads();
        if (tid == 0) {
            float s = 0.0f;
            #pragma unroll
            for (int wI = 0; wI < 4; wI++) s += wsum[wI];
            *ent = s;
            g_done = 0;
        }
    }
}

// ---------------------------------------------------------------------------
extern "C" void kernel_launch(void* const* d_in, const int* in_sizes, int n_in,
                              void* d_out, int out_size) {
    const float* x;
    const float* emb;
    if (in_sizes[0] == NS_TOTAL * VDIM) {
        x   = (const float*)d_in[0];
        emb = (const float*)d_in[1];
    } else {
        x   = (const float*)d_in[1];
        emb = (const float*)d_in[0];
    }

    float* out0 = (float*)d_out;                        // 65536*64
    float* out1 = out0 + (size_t)NS_TOTAL * VDIM;       // 65536
    float* out2 = out1 + NS_TOTAL;                      // 65536
    float* ent  = out2 + NS_TOTAL;                      // 1

    cudaFuncSetAttribute(vq_main_kernel,
                         cudaFuncAttributeMaxDynamicSharedMemorySize, SMEM_BYTES);

    vq_prep_kernel<<<16, 256>>>(emb);
    vq_main_kernel<<<GRID, THREADS, SMEM_BYTES>>>(x, emb, out0, out1, out2, ent);
}